// round 1
// baseline (speedup 1.0000x reference)
#include <cuda_runtime.h>

// Affine-collapse: the 4-layer no-activation MLP is weight(x) = alpha*x + beta.
// out[row] = alpha * S2/S1^2 + beta, with S1 = sum(x), S2 = sum(x^2).

#define HIDDEN 32
#define L 2048          // elements per ragged row
#define L_VEC4 (L / 4)  // 512 float4 per row

__device__ float g_alpha;
__device__ float g_beta;

// ---- Prologue: fold weights into (alpha, beta). 1 block, 32 threads. ----
__global__ void collapse_mlp_kernel(const float* __restrict__ w1,
                                    const float* __restrict__ b1,
                                    const float* __restrict__ w2,
                                    const float* __restrict__ b2,
                                    const float* __restrict__ w3,
                                    const float* __restrict__ b3,
                                    const float* __restrict__ w4,
                                    const float* __restrict__ b4) {
    const int h = threadIdx.x;  // 0..31
    __shared__ float v1[HIDDEN], c1[HIDDEN];
    __shared__ float v2[HIDDEN], c2[HIDDEN];

    // layer 1: h1 = x*w1 + b1  -> slope v1, intercept c1 (per hidden unit)
    v1[h] = w1[h];
    c1[h] = b1[h];
    __syncthreads();

    // layer 2: h2_k = sum_h h1_h * w2[h,k] + b2_k
    float sv = 0.f, sc = 0.f;
    #pragma unroll
    for (int i = 0; i < HIDDEN; i++) {
        const float w = w2[i * HIDDEN + h];
        sv += v1[i] * w;
        sc += c1[i] * w;
    }
    v2[h] = sv;
    c2[h] = sc + b2[h];
    __syncthreads();

    // layer 3
    sv = 0.f; sc = 0.f;
    #pragma unroll
    for (int i = 0; i < HIDDEN; i++) {
        const float w = w3[i * HIDDEN + h];
        sv += v2[i] * w;
        sc += c2[i] * w;
    }
    const float v3 = sv;
    const float c3 = sc + b3[h];

    // layer 4: alpha = sum_h v3_h * w4_h ; beta = sum_h c3_h * w4_h + b4
    float a = v3 * w4[h];
    float b = c3 * w4[h];
    #pragma unroll
    for (int off = 16; off > 0; off >>= 1) {
        a += __shfl_xor_sync(0xffffffffu, a, off);
        b += __shfl_xor_sync(0xffffffffu, b, off);
    }
    if (h == 0) {
        g_alpha = a;
        g_beta  = b + b4[0];
    }
}

// ---- Main pass: one block per row, 256 threads, 2 float4 loads/thread. ----
__global__ __launch_bounds__(256) void row_reduce_kernel(const float4* __restrict__ x,
                                                         float* __restrict__ out) {
    const int row = blockIdx.x;
    const float4* __restrict__ p = x + (size_t)row * L_VEC4;
    const int t = threadIdx.x;

    float s1 = 0.f, s2 = 0.f;
    #pragma unroll
    for (int i = 0; i < L_VEC4 / 256; i++) {
        const float4 v = p[t + i * 256];
        s1 += (v.x + v.y) + (v.z + v.w);
        s2 += (v.x * v.x + v.y * v.y) + (v.z * v.z + v.w * v.w);
    }

    // warp reduce
    #pragma unroll
    for (int off = 16; off > 0; off >>= 1) {
        s1 += __shfl_xor_sync(0xffffffffu, s1, off);
        s2 += __shfl_xor_sync(0xffffffffu, s2, off);
    }

    __shared__ float sh1[8], sh2[8];
    const int w = t >> 5, l = t & 31;
    if (l == 0) { sh1[w] = s1; sh2[w] = s2; }
    __syncthreads();

    if (t < 8) {
        float a = sh1[t], b = sh2[t];
        #pragma unroll
        for (int off = 4; off > 0; off >>= 1) {
            a += __shfl_xor_sync(0xffu, a, off);
            b += __shfl_xor_sync(0xffu, b, off);
        }
        if (t == 0) {
            out[row] = g_alpha * b / (a * a) + g_beta;
        }
    }
}

extern "C" void kernel_launch(void* const* d_in, const int* in_sizes, int n_in,
                              void* d_out, int out_size) {
    const float* inc_m = (const float*)d_in[0];
    const float* w1 = (const float*)d_in[1];
    const float* b1 = (const float*)d_in[2];
    const float* w2 = (const float*)d_in[3];
    const float* b2 = (const float*)d_in[4];
    const float* w3 = (const float*)d_in[5];
    const float* b3 = (const float*)d_in[6];
    const float* w4 = (const float*)d_in[7];
    const float* b4 = (const float*)d_in[8];
    float* out = (float*)d_out;

    const int rows = in_sizes[0] / L;  // B*F = 2048

    collapse_mlp_kernel<<<1, 32>>>(w1, b1, w2, b2, w3, b3, w4, b4);
    row_reduce_kernel<<<rows, 256>>>((const float4*)inc_m, out);
}

// round 2
// speedup vs baseline: 1.2399x; 1.2399x over previous
#include <cuda_runtime.h>

// Affine-collapse: weight(x) = alpha*x + beta (4-layer affine MLP, no activations).
// out[row] = alpha * S2/S1^2 + beta, S1 = sum(x), S2 = sum(x^2), row = 2048 floats.
//
// Single fused kernel: warp 0 of each block recomputes (alpha, beta) from the
// tiny weight tensors (L2-resident after first block); every other warp streams
// one row with 16 independent LDG.128s per lane and reduces via shuffles.

#define HIDDEN 32
#define L 2048
#define L_VEC4 (L / 4)          // 512 float4 per row
#define WARPS_PER_BLOCK 8
#define THREADS (WARPS_PER_BLOCK * 32)
#define F4_PER_LANE (L_VEC4 / 32)  // 16

__global__ __launch_bounds__(THREADS) void incidence_fused_kernel(
    const float4* __restrict__ x,
    const float* __restrict__ w1, const float* __restrict__ b1,
    const float* __restrict__ w2, const float* __restrict__ b2,
    const float* __restrict__ w3, const float* __restrict__ b3,
    const float* __restrict__ w4, const float* __restrict__ b4,
    float* __restrict__ out, int rows)
{
    __shared__ float sh_alpha, sh_beta;

    const int t   = threadIdx.x;
    const int wid = t >> 5;
    const int lid = t & 31;

    // ---- warp 0: collapse the affine stack into (alpha, beta) via shuffles ----
    if (wid == 0) {
        const unsigned m = 0xffffffffu;
        float v1 = w1[lid];
        float c1 = b1[lid];

        float sv = 0.f, sc = 0.f;
        #pragma unroll
        for (int i = 0; i < HIDDEN; i++) {
            const float w = w2[i * HIDDEN + lid];
            sv += __shfl_sync(m, v1, i) * w;
            sc += __shfl_sync(m, c1, i) * w;
        }
        const float v2 = sv;
        const float c2 = sc + b2[lid];

        sv = 0.f; sc = 0.f;
        #pragma unroll
        for (int i = 0; i < HIDDEN; i++) {
            const float w = w3[i * HIDDEN + lid];
            sv += __shfl_sync(m, v2, i) * w;
            sc += __shfl_sync(m, c2, i) * w;
        }
        const float v3 = sv;
        const float c3 = sc + b3[lid];

        float a = v3 * w4[lid];
        float b = c3 * w4[lid];
        #pragma unroll
        for (int off = 16; off > 0; off >>= 1) {
            a += __shfl_xor_sync(m, a, off);
            b += __shfl_xor_sync(m, b, off);
        }
        if (lid == 0) {
            sh_alpha = a;
            sh_beta  = b + b4[0];
        }
    }

    // ---- each warp streams one full row ----
    const int row = blockIdx.x * WARPS_PER_BLOCK + wid;
    float s1 = 0.f, s2 = 0.f;

    if (row < rows) {
        const float4* __restrict__ p = x + (size_t)row * L_VEC4 + lid;
        #pragma unroll
        for (int i = 0; i < F4_PER_LANE; i++) {
            const float4 v = p[i * 32];
            s1 += (v.x + v.y) + (v.z + v.w);
            s2 += (v.x * v.x + v.y * v.y) + (v.z * v.z + v.w * v.w);
        }
        #pragma unroll
        for (int off = 16; off > 0; off >>= 1) {
            s1 += __shfl_xor_sync(0xffffffffu, s1, off);
            s2 += __shfl_xor_sync(0xffffffffu, s2, off);
        }
    }

    __syncthreads();  // publish sh_alpha / sh_beta

    if (row < rows && lid == 0) {
        out[row] = sh_alpha * s2 / (s1 * s1) + sh_beta;
    }
}

extern "C" void kernel_launch(void* const* d_in, const int* in_sizes, int n_in,
                              void* d_out, int out_size) {
    const float* inc_m = (const float*)d_in[0];
    const float* w1 = (const float*)d_in[1];
    const float* b1 = (const float*)d_in[2];
    const float* w2 = (const float*)d_in[3];
    const float* b2 = (const float*)d_in[4];
    const float* w3 = (const float*)d_in[5];
    const float* b3 = (const float*)d_in[6];
    const float* w4 = (const float*)d_in[7];
    const float* b4 = (const float*)d_in[8];
    float* out = (float*)d_out;

    const int rows = in_sizes[0] / L;  // B*F = 2048
    const int blocks = (rows + WARPS_PER_BLOCK - 1) / WARPS_PER_BLOCK;

    incidence_fused_kernel<<<blocks, THREADS>>>(
        (const float4*)inc_m, w1, b1, w2, b2, w3, b3, w4, b4, out, rows);
}